// round 3
// baseline (speedup 1.0000x reference)
#include <cuda_runtime.h>
#include <cstdint>

#define B_ 4
#define T_ 256
#define U_ 64
#define D_ 512
#define H_ 512
#define V_ 1024

// Scratch (allocation-free rule: __device__ globals)
__device__ float g_enc[B_ * T_ * H_];   // 1024 x 512  enc_proj
__device__ float g_dec[B_ * U_ * H_];   // 256  x 512  dec_proj + b1

__device__ __forceinline__ uint32_t f2tf32(float x) {
    uint32_t u;
    asm("cvt.rna.tf32.f32 %0, %1;" : "=r"(u) : "f"(x));
    return u;
}

__device__ __forceinline__ float tanh_fast(float x) {
    float y;
    asm("tanh.approx.f32 %0, %1;" : "=f"(y) : "f"(x));
    return y;
}

__device__ __forceinline__ float gelu_tanh(float x) {
    const float c = 0.7978845608028654f;   // sqrt(2/pi)
    float t = c * (x + 0.044715f * x * x * x);
    return 0.5f * x * (1.0f + tanh_fast(t));
}

__device__ __forceinline__ void mma_tf32(float* acc, uint32_t a0, uint32_t a1,
                                         uint32_t a2, uint32_t a3,
                                         uint32_t b0, uint32_t b1) {
    asm volatile(
        "mma.sync.aligned.m16n8k8.row.col.f32.tf32.tf32.f32 "
        "{%0,%1,%2,%3}, {%4,%5,%6,%7}, {%8,%9}, {%0,%1,%2,%3};"
        : "+f"(acc[0]), "+f"(acc[1]), "+f"(acc[2]), "+f"(acc[3])
        : "r"(a0), "r"(a1), "r"(a2), "r"(a3), "r"(b0), "r"(b1));
}

// ---------------------------------------------------------------------------
// Projection GEMM: out[m,h] = sum_d A[m,d] * W[h*1024 + d] (+ bias[h])
// Tile M=64, N=128, KC=32. which: 0 -> g_enc, 1 -> g_dec.
// ---------------------------------------------------------------------------
__global__ __launch_bounds__(256) void proj_kernel(
    const float* __restrict__ A, const float* __restrict__ W,
    const float* __restrict__ bias, int which)
{
    float* out = which ? g_dec : g_enc;
    __shared__ uint32_t As[64][33];
    __shared__ uint32_t Bs[128][33];

    const int tid  = threadIdx.x;
    const int lane = tid & 31;
    const int w    = tid >> 5;
    const int wm   = w >> 1;      // 0..3 (16 rows each)
    const int wn   = w & 1;       // 0..1 (64 cols each)
    const int m0   = blockIdx.y * 64;
    const int n0   = blockIdx.x * 128;

    float acc[8][4] = {};

    for (int k0 = 0; k0 < D_; k0 += 32) {
        __syncthreads();
        // A tile: 64x32, 8 elems/thread
        {
            int r  = tid >> 2;
            int kb = (tid & 3) * 8;
            const float* src = A + (m0 + r) * D_ + k0 + kb;
            float4 v0 = *(const float4*)(src);
            float4 v1 = *(const float4*)(src + 4);
            As[r][kb + 0] = f2tf32(v0.x); As[r][kb + 1] = f2tf32(v0.y);
            As[r][kb + 2] = f2tf32(v0.z); As[r][kb + 3] = f2tf32(v0.w);
            As[r][kb + 4] = f2tf32(v1.x); As[r][kb + 5] = f2tf32(v1.y);
            As[r][kb + 6] = f2tf32(v1.z); As[r][kb + 7] = f2tf32(v1.w);
        }
        // B tile: 128x32, 16 elems/thread (W row stride = 2*D = 1024)
        {
            int n  = tid >> 1;
            int kb = (tid & 1) * 16;
            const float* src = W + (n0 + n) * (2 * D_) + k0 + kb;
            #pragma unroll
            for (int i = 0; i < 16; i += 4) {
                float4 v = *(const float4*)(src + i);
                Bs[n][kb + i + 0] = f2tf32(v.x);
                Bs[n][kb + i + 1] = f2tf32(v.y);
                Bs[n][kb + i + 2] = f2tf32(v.z);
                Bs[n][kb + i + 3] = f2tf32(v.w);
            }
        }
        __syncthreads();

        #pragma unroll
        for (int kk = 0; kk < 4; kk++) {
            int ar = wm * 16 + (lane >> 2);
            int ac = kk * 8 + (lane & 3);
            uint32_t a0 = As[ar][ac];
            uint32_t a1 = As[ar + 8][ac];
            uint32_t a2 = As[ar][ac + 4];
            uint32_t a3 = As[ar + 8][ac + 4];
            #pragma unroll
            for (int nf = 0; nf < 8; nf++) {
                int br = wn * 64 + nf * 8 + (lane >> 2);
                uint32_t b0 = Bs[br][ac];
                uint32_t b1v = Bs[br][ac + 4];
                mma_tf32(acc[nf], a0, a1, a2, a3, b0, b1v);
            }
        }
    }

    // Epilogue
    int row = m0 + wm * 16 + (lane >> 2);
    #pragma unroll
    for (int nf = 0; nf < 8; nf++) {
        int cg = n0 + wn * 64 + nf * 8 + (lane & 3) * 2;
        float bv0 = bias ? bias[cg]     : 0.0f;
        float bv1 = bias ? bias[cg + 1] : 0.0f;
        out[row * H_ + cg]           = acc[nf][0] + bv0;
        out[row * H_ + cg + 1]       = acc[nf][1] + bv1;
        out[(row + 8) * H_ + cg]     = acc[nf][2] + bv0;
        out[(row + 8) * H_ + cg + 1] = acc[nf][3] + bv1;
    }
}

// ---------------------------------------------------------------------------
// Fused GELU + big GEMM.
// logits[bt*64+u, v] = sum_h gelu(enc[bt,h] + dec[b*64+u,h]) * w2[v,h]
// Tile M=128 (two bt), N=128, KC=32. 8 warps: 4(m: 32 rows) x 2(n: 64 cols).
// ---------------------------------------------------------------------------
__global__ __launch_bounds__(256) void joint_kernel(
    const float* __restrict__ w2, float* __restrict__ out)
{
    __shared__ uint32_t As[128][33];
    __shared__ uint32_t Bs[128][33];

    const int tid  = threadIdx.x;
    const int lane = tid & 31;
    const int w    = tid >> 5;
    const int wm   = w >> 1;      // 0..3, 32 rows each (2 m-frags)
    const int wn   = w & 1;       // 0..1, 64 cols each
    const int yt   = blockIdx.y;  // 0..511
    const int bt0  = yt * 2;
    const int b    = bt0 >> 8;    // /T_
    const int n0   = blockIdx.x * 128;

    float acc[2][8][4] = {};

    for (int k0 = 0; k0 < H_; k0 += 32) {
        __syncthreads();
        // A tile: generate hidden = gelu(enc + dec) in tf32. 16 elems/thread.
        {
            int r  = tid >> 1;           // 0..127
            int kb = (tid & 1) * 16;
            int bt = bt0 + (r >> 6);
            int u  = r & 63;
            const float* ep = g_enc + bt * H_ + k0 + kb;
            const float* dp = g_dec + (b * 64 + u) * H_ + k0 + kb;
            #pragma unroll
            for (int i = 0; i < 16; i += 4) {
                float4 e = *(const float4*)(ep + i);
                float4 d = *(const float4*)(dp + i);
                As[r][kb + i + 0] = f2tf32(gelu_tanh(e.x + d.x));
                As[r][kb + i + 1] = f2tf32(gelu_tanh(e.y + d.y));
                As[r][kb + i + 2] = f2tf32(gelu_tanh(e.z + d.z));
                As[r][kb + i + 3] = f2tf32(gelu_tanh(e.w + d.w));
            }
        }
        // B tile: w2 rows. 16 elems/thread.
        {
            int n  = tid >> 1;
            int kb = (tid & 1) * 16;
            const float* src = w2 + (n0 + n) * H_ + k0 + kb;
            #pragma unroll
            for (int i = 0; i < 16; i += 4) {
                float4 v = *(const float4*)(src + i);
                Bs[n][kb + i + 0] = f2tf32(v.x);
                Bs[n][kb + i + 1] = f2tf32(v.y);
                Bs[n][kb + i + 2] = f2tf32(v.z);
                Bs[n][kb + i + 3] = f2tf32(v.w);
            }
        }
        __syncthreads();

        #pragma unroll
        for (int kk = 0; kk < 4; kk++) {
            int ac = kk * 8 + (lane & 3);
            uint32_t bb[8][2];
            #pragma unroll
            for (int nf = 0; nf < 8; nf++) {
                int br = wn * 64 + nf * 8 + (lane >> 2);
                bb[nf][0] = Bs[br][ac];
                bb[nf][1] = Bs[br][ac + 4];
            }
            #pragma unroll
            for (int mf = 0; mf < 2; mf++) {
                int ar = wm * 32 + mf * 16 + (lane >> 2);
                uint32_t a0 = As[ar][ac];
                uint32_t a1 = As[ar + 8][ac];
                uint32_t a2 = As[ar][ac + 4];
                uint32_t a3 = As[ar + 8][ac + 4];
                #pragma unroll
                for (int nf = 0; nf < 8; nf++)
                    mma_tf32(acc[mf][nf], a0, a1, a2, a3, bb[nf][0], bb[nf][1]);
            }
        }
    }

    // Epilogue: out rows are linear (yt*128 + row) since U_ == 64 tiles pack.
    const int rowbase = yt * 128;
    #pragma unroll
    for (int mf = 0; mf < 2; mf++) {
        int r0 = wm * 32 + mf * 16 + (lane >> 2);
        #pragma unroll
        for (int nf = 0; nf < 8; nf++) {
            int cg = n0 + wn * 64 + nf * 8 + (lane & 3) * 2;
            float2 v0 = make_float2(acc[mf][nf][0], acc[mf][nf][1]);
            float2 v1 = make_float2(acc[mf][nf][2], acc[mf][nf][3]);
            *(float2*)(out + (size_t)(rowbase + r0) * V_ + cg)     = v0;
            *(float2*)(out + (size_t)(rowbase + r0 + 8) * V_ + cg) = v1;
        }
    }
}

extern "C" void kernel_launch(void* const* d_in, const int* in_sizes, int n_in,
                              void* d_out, int out_size) {
    const float* enc = (const float*)d_in[0];  // (4,256,512)
    const float* dec = (const float*)d_in[1];  // (4,64,512)
    const float* w1  = (const float*)d_in[2];  // (512,1024)
    const float* b1  = (const float*)d_in[3];  // (512)
    const float* w2  = (const float*)d_in[4];  // (1024,512)
    float* out = (float*)d_out;                // (4,256,64,1024)

    // enc_proj: M=1024 rows, W = w1[:, :512]
    proj_kernel<<<dim3(H_ / 128, (B_ * T_) / 64), 256>>>(enc, w1, nullptr, 0);
    // dec_proj + b1: M=256 rows, W = w1[:, 512:]
    proj_kernel<<<dim3(H_ / 128, (B_ * U_) / 64), 256>>>(dec, w1 + D_, b1, 1);
    // fused gelu + [65536,512]x[512,1024] GEMM
    joint_kernel<<<dim3(V_ / 128, (B_ * T_) / 2), 256>>>(w2, out);
}